// round 3
// baseline (speedup 1.0000x reference)
#include <cuda_runtime.h>
#include <cuda_bf16.h>

// Problem constants (fixed per reference: N=131072, C=1024, D=128)
#define NROWS 131072
#define CROWS 1024
#define DDIM  128

#define BM 128
#define BN 128
#define BK 16
#define TM 8
#define TN 8

// Scratch for row norms (no cudaMalloc allowed).
__device__ float g_xsq[NROWS];
__device__ float g_wsq[CROWS];

// ---------------------------------------------------------------------------
// Kernel 1: per-row squared norms for X and W. One warp per row.
// ---------------------------------------------------------------------------
__global__ void norms_kernel(const float* __restrict__ x,
                             const float* __restrict__ w) {
    const int gwarp = (blockIdx.x * blockDim.x + threadIdx.x) >> 5;
    const int lane  = threadIdx.x & 31;
    const int total = NROWS + CROWS;
    if (gwarp >= total) return;

    const float* base = (gwarp < NROWS)
        ? (x + (size_t)gwarp * DDIM)
        : (w + (size_t)(gwarp - NROWS) * DDIM);

    // 32 lanes x float4 = 128 floats = one full row
    float4 v = reinterpret_cast<const float4*>(base)[lane];
    float s = v.x * v.x + v.y * v.y + v.z * v.z + v.w * v.w;

    #pragma unroll
    for (int o = 16; o > 0; o >>= 1)
        s += __shfl_xor_sync(0xffffffffu, s, o);

    if (lane == 0) {
        if (gwarp < NROWS) g_xsq[gwarp] = s;
        else               g_wsq[gwarp - NROWS] = s;
    }
}

// ---------------------------------------------------------------------------
// Kernel 2: tiled "GEMM-like" distance kernel.
//   dist[n,c] = xsq[n] + wsq[c] - 2 * sum_d X[n,d]*W[c,d]
// 128x128 block tile, BK=16 K-chunks (8 iterations over D=128),
// 256 threads, 8x8 per-thread register tile.
// ---------------------------------------------------------------------------
__global__ __launch_bounds__(256, 2)
void dist_kernel(const float* __restrict__ X,
                 const float* __restrict__ W,
                 float* __restrict__ out) {
    __shared__ float As[BK][BM];   // transposed: As[k][m]
    __shared__ float Bs[BK][BN];   // transposed: Bs[k][n]

    const int tid = threadIdx.x;
    const int tx  = tid & 15;      // 16 cols of threads
    const int ty  = tid >> 4;      // 16 rows of threads
    const int bm  = blockIdx.y * BM;
    const int bn  = blockIdx.x * BN;

    float acc[TM][TN];
    #pragma unroll
    for (int i = 0; i < TM; i++)
        #pragma unroll
        for (int j = 0; j < TN; j++)
            acc[i][j] = 0.0f;

    #pragma unroll
    for (int kc = 0; kc < DDIM; kc += BK) {
        // Load A tile (128 rows x 16 k) and B tile, transposed into smem.
        // 512 float4 loads each; 2 per thread.
        #pragma unroll
        for (int r = 0; r < 2; r++) {
            const int idx = tid + r * 256;   // 0..511
            const int row = idx >> 2;        // 0..127
            const int c4  = idx & 3;         // 0..3 (float4 within 16 k)

            float4 av = *reinterpret_cast<const float4*>(
                X + (size_t)(bm + row) * DDIM + kc + c4 * 4);
            As[c4 * 4 + 0][row] = av.x;
            As[c4 * 4 + 1][row] = av.y;
            As[c4 * 4 + 2][row] = av.z;
            As[c4 * 4 + 3][row] = av.w;

            float4 bv = *reinterpret_cast<const float4*>(
                W + (size_t)(bn + row) * DDIM + kc + c4 * 4);
            Bs[c4 * 4 + 0][row] = bv.x;
            Bs[c4 * 4 + 1][row] = bv.y;
            Bs[c4 * 4 + 2][row] = bv.z;
            Bs[c4 * 4 + 3][row] = bv.w;
        }
        __syncthreads();

        #pragma unroll
        for (int k = 0; k < BK; k++) {
            float a[TM], b[TN];
            const float4* arow = reinterpret_cast<const float4*>(&As[k][0]);
            const float4* brow = reinterpret_cast<const float4*>(&Bs[k][0]);
            float4 a0 = arow[ty * 2 + 0];
            float4 a1 = arow[ty * 2 + 1];
            float4 b0 = brow[tx * 2 + 0];
            float4 b1 = brow[tx * 2 + 1];
            a[0] = a0.x; a[1] = a0.y; a[2] = a0.z; a[3] = a0.w;
            a[4] = a1.x; a[5] = a1.y; a[6] = a1.z; a[7] = a1.w;
            b[0] = b0.x; b[1] = b0.y; b[2] = b0.z; b[3] = b0.w;
            b[4] = b1.x; b[5] = b1.y; b[6] = b1.z; b[7] = b1.w;

            #pragma unroll
            for (int i = 0; i < TM; i++)
                #pragma unroll
                for (int j = 0; j < TN; j++)
                    acc[i][j] = fmaf(a[i], b[j], acc[i][j]);
        }
        __syncthreads();
    }

    // Epilogue: dist = xsq + wsq - 2*acc, vectorized stores.
    float wsq[TN];
    #pragma unroll
    for (int j = 0; j < TN; j++)
        wsq[j] = g_wsq[bn + tx * TN + j];

    #pragma unroll
    for (int i = 0; i < TM; i++) {
        const int row = bm + ty * TM + i;
        const float xs = g_xsq[row];
        float4 o0, o1;
        o0.x = xs + wsq[0] - 2.0f * acc[i][0];
        o0.y = xs + wsq[1] - 2.0f * acc[i][1];
        o0.z = xs + wsq[2] - 2.0f * acc[i][2];
        o0.w = xs + wsq[3] - 2.0f * acc[i][3];
        o1.x = xs + wsq[4] - 2.0f * acc[i][4];
        o1.y = xs + wsq[5] - 2.0f * acc[i][5];
        o1.z = xs + wsq[6] - 2.0f * acc[i][6];
        o1.w = xs + wsq[7] - 2.0f * acc[i][7];
        float4* orow = reinterpret_cast<float4*>(
            out + (size_t)row * CROWS + bn + tx * TN);
        orow[0] = o0;
        orow[1] = o1;
    }
}

// ---------------------------------------------------------------------------
extern "C" void kernel_launch(void* const* d_in, const int* in_sizes, int n_in,
                              void* d_out, int out_size) {
    const float* x = (const float*)d_in[0];   // [N, D]
    const float* w = (const float*)d_in[1];   // [C, D]
    float* out = (float*)d_out;               // [N, C]

    // Norms: one warp per row, 8 warps per block.
    const int total_rows = NROWS + CROWS;
    const int warps_per_block = 256 / 32;
    const int nblocks = (total_rows + warps_per_block - 1) / warps_per_block;
    norms_kernel<<<nblocks, 256>>>(x, w);

    dim3 grid(CROWS / BN, NROWS / BM);  // (8, 1024)
    dist_kernel<<<grid, 256>>>(x, w, out);
}

// round 5
// speedup vs baseline: 2.2243x; 2.2243x over previous
#include <cuda_runtime.h>
#include <cuda_bf16.h>
#include <cstdint>

// Problem constants (fixed: N=131072, C=1024, D=128)
#define NROWS 131072
#define CROWS 1024
#define DDIM  128
#define KSPLIT 256           // hi|lo concatenated along K

#define BM 128
#define BN 128
#define BKC 64               // k per chunk (bf16) -> 128B rows (SW128 swizzle)
#define NCHUNK (KSPLIT / BKC)   // 4
#define STAGES 3
#define STAGE_BYTES 32768    // A tile 16KB + B tile 16KB
#define SMEM_NEED (STAGES * STAGE_BYTES)

// ---------------------------------------------------------------------------
// Device scratch (no cudaMalloc allowed)
// ---------------------------------------------------------------------------
__device__ float g_xsq[NROWS];
__device__ float g_wsq[CROWS];
__device__ __nv_bfloat16 g_xb[(size_t)NROWS * KSPLIT];  // [N,256]: 0-127 hi, 128-255 lo
__device__ __nv_bfloat16 g_wb[(size_t)CROWS * KSPLIT];  // [C,256]

// ---------------------------------------------------------------------------
// PTX helpers — base-target-safe only (NO tcgen05: harness compiles PTX for
// plain sm_103, arch-specific 'a' features are rejected by ptxas).
// ---------------------------------------------------------------------------
__device__ __forceinline__ uint32_t smem_u32(const void* p) {
    uint32_t a;
    asm("{ .reg .u64 t; cvta.to.shared.u64 t, %1; cvt.u32.u64 %0, t; }"
        : "=r"(a) : "l"(p));
    return a;
}

__device__ __forceinline__ void cp_async16(uint32_t dst, const void* src) {
    asm volatile("cp.async.cg.shared.global [%0], [%1], 16;"
                 :: "r"(dst), "l"(src));
}
#define CP_COMMIT() asm volatile("cp.async.commit_group;" ::: "memory")
#define CP_WAIT1()  asm volatile("cp.async.wait_group 1;" ::: "memory")

__device__ __forceinline__ void ldsm_x4(uint32_t& r0, uint32_t& r1,
                                        uint32_t& r2, uint32_t& r3, uint32_t a) {
    asm volatile("ldmatrix.sync.aligned.m8n8.x4.shared.b16 {%0,%1,%2,%3}, [%4];"
                 : "=r"(r0), "=r"(r1), "=r"(r2), "=r"(r3) : "r"(a));
}
__device__ __forceinline__ void ldsm_x2(uint32_t& r0, uint32_t& r1, uint32_t a) {
    asm volatile("ldmatrix.sync.aligned.m8n8.x2.shared.b16 {%0,%1}, [%2];"
                 : "=r"(r0), "=r"(r1) : "r"(a));
}

__device__ __forceinline__ void mma16816(float* c, const uint32_t* a,
                                         const uint32_t* b) {
    asm volatile(
        "mma.sync.aligned.m16n8k16.row.col.f32.bf16.bf16.f32 "
        "{%0,%1,%2,%3}, {%4,%5,%6,%7}, {%8,%9}, {%0,%1,%2,%3};"
        : "+f"(c[0]), "+f"(c[1]), "+f"(c[2]), "+f"(c[3])
        : "r"(a[0]), "r"(a[1]), "r"(a[2]), "r"(a[3]), "r"(b[0]), "r"(b[1]));
}

// SW128 swizzle: 16B-unit index (bits 4-6) ^= row&7 (bits 7-9)
__device__ __forceinline__ uint32_t swz(uint32_t b) {
    return b ^ ((b >> 3) & 0x70u);
}

// ---------------------------------------------------------------------------
// Kernel 1: fp32 -> split-bf16 conversion + exact fp32 row norms.
// One warp per row (X rows then W rows).
// ---------------------------------------------------------------------------
__global__ __launch_bounds__(256)
void convert_kernel(const float* __restrict__ x, const float* __restrict__ w) {
    const int gwarp = (blockIdx.x * blockDim.x + threadIdx.x) >> 5;
    const int lane  = threadIdx.x & 31;
    if (gwarp >= NROWS + CROWS) return;

    const bool isx = gwarp < NROWS;
    const int r = isx ? gwarp : gwarp - NROWS;
    const float* base = isx ? (x + (size_t)r * DDIM) : (w + (size_t)r * DDIM);

    float4 v = reinterpret_cast<const float4*>(base)[lane];
    float f[4] = {v.x, v.y, v.z, v.w};

    float s = f[0]*f[0] + f[1]*f[1] + f[2]*f[2] + f[3]*f[3];
    #pragma unroll
    for (int o = 16; o > 0; o >>= 1)
        s += __shfl_xor_sync(0xffffffffu, s, o);

    uint32_t hb[4], lb[4];
    #pragma unroll
    for (int i = 0; i < 4; i++) {
        __nv_bfloat16 h = __float2bfloat16_rn(f[i]);
        float lo = f[i] - __bfloat162float(h);
        __nv_bfloat16 l = __float2bfloat16_rn(lo);
        hb[i] = (uint32_t)__bfloat16_as_ushort(h);
        lb[i] = (uint32_t)__bfloat16_as_ushort(l);
    }
    uint2 H, L;
    H.x = hb[0] | (hb[1] << 16); H.y = hb[2] | (hb[3] << 16);
    L.x = lb[0] | (lb[1] << 16); L.y = lb[2] | (lb[3] << 16);

    __nv_bfloat16* dst = isx ? (g_xb + (size_t)r * KSPLIT) : (g_wb + (size_t)r * KSPLIT);
    reinterpret_cast<uint2*>(dst)[lane]        = H;
    reinterpret_cast<uint2*>(dst + DDIM)[lane] = L;

    if (lane == 0) {
        if (isx) g_xsq[r] = s; else g_wsq[r] = s;
    }
}

// ---------------------------------------------------------------------------
// Kernel 2: bf16 split GEMM via mma.sync (m16n8k16) + fused distance epilogue.
// CTA 128x128, K=256 in 4 chunks of 64, 3-stage cp.async pipeline.
// 8 warps: warp_m in {0,1} (64 rows), warp_n in {0..3} (32 cols).
// ---------------------------------------------------------------------------
__global__ __launch_bounds__(256, 2)
void mma_dist_kernel(float* __restrict__ out) {
    extern __shared__ char sdyn[];
    const uint32_t sb = smem_u32(sdyn);

    const int tid    = threadIdx.x;
    const int lane   = tid & 31;
    const int wid    = tid >> 5;
    const int warp_m = wid & 1;        // 0..1 -> 64-row half
    const int warp_n = wid >> 1;       // 0..3 -> 32-col quarter
    const int bn     = blockIdx.x * BN;  // prototypes (8 tiles)
    const int bm     = blockIdx.y * BM;  // x rows (1024 tiles)

    // per-thread cp.async job decomposition: 1024 16B-chunks per tile, 4/thread
    // c = tid + i*256; m = c>>3 (row), u = c&7 (16B unit)
    uint32_t cp_dst_off[4];
    const __nv_bfloat16* cp_srcA[4];
    const __nv_bfloat16* cp_srcB[4];
    #pragma unroll
    for (int i = 0; i < 4; i++) {
        const int c = tid + i * 256;
        const int m = c >> 3, u = c & 7;
        cp_dst_off[i] = swz((uint32_t)(m * 128 + u * 16));
        cp_srcA[i] = g_xb + (size_t)(bm + m) * KSPLIT + u * 8;
        cp_srcB[i] = g_wb + (size_t)(bn + m) * KSPLIT + u * 8;
    }

    // prologue: issue chunks 0 and 1 into stages 0,1
    #pragma unroll
    for (int s = 0; s < 2; s++) {
        const uint32_t Ab = sb + s * STAGE_BYTES;
        const uint32_t Bb = Ab + 16384;
        #pragma unroll
        for (int i = 0; i < 4; i++) {
            cp_async16(Ab + cp_dst_off[i], cp_srcA[i] + s * BKC);
            cp_async16(Bb + cp_dst_off[i], cp_srcB[i] + s * BKC);
        }
        CP_COMMIT();
    }

    float acc[4][4][4];
    #pragma unroll
    for (int mi = 0; mi < 4; mi++)
        #pragma unroll
        for (int ni = 0; ni < 4; ni++)
            #pragma unroll
            for (int q = 0; q < 4; q++)
                acc[mi][ni][q] = 0.0f;

    // ldmatrix lane-address components
    const int a_row = warp_m * 64 + (lane & 15);  // + mi*16
    const int a_u   = lane >> 4;                  // + ks*2
    const int b_row = warp_n * 32 + (lane & 7);   // + ni*8
    const int b_u   = (lane >> 3) & 1;            // + ks*2

    for (int ch = 0; ch < NCHUNK; ch++) {
        CP_WAIT1();
        __syncthreads();

        // issue chunk ch+2 into stage (ch+2)%3 (that stage was consumed at ch-1)
        if (ch + 2 < NCHUNK) {
            const int s = (ch + 2) % STAGES;
            const uint32_t Ab = sb + s * STAGE_BYTES;
            const uint32_t Bb = Ab + 16384;
            #pragma unroll
            for (int i = 0; i < 4; i++) {
                cp_async16(Ab + cp_dst_off[i], cp_srcA[i] + (ch + 2) * BKC);
                cp_async16(Bb + cp_dst_off[i], cp_srcB[i] + (ch + 2) * BKC);
            }
        }
        CP_COMMIT();

        const uint32_t Ab = sb + (ch % STAGES) * STAGE_BYTES;
        const uint32_t Bb = Ab + 16384;

        #pragma unroll
        for (int ks = 0; ks < 4; ks++) {
            uint32_t a[4][4], b[4][2];
            #pragma unroll
            for (int mi = 0; mi < 4; mi++) {
                const uint32_t addr = Ab + swz(
                    (uint32_t)((a_row + mi * 16) * 128 + (a_u + ks * 2) * 16));
                ldsm_x4(a[mi][0], a[mi][1], a[mi][2], a[mi][3], addr);
            }
            #pragma unroll
            for (int ni = 0; ni < 4; ni++) {
                const uint32_t addr = Bb + swz(
                    (uint32_t)((b_row + ni * 8) * 128 + (b_u + ks * 2) * 16));
                ldsm_x2(b[ni][0], b[ni][1], addr);
            }
            #pragma unroll
            for (int mi = 0; mi < 4; mi++)
                #pragma unroll
                for (int ni = 0; ni < 4; ni++)
                    mma16816(acc[mi][ni], a[mi], b[ni]);
        }
        __syncthreads();
    }

    // ---- Epilogue: dist = xsq + wsq - 2*acc ----
    // thread owns: rows r0 = warp_m*64+mi*16+lane/4, r1 = r0+8;
    //              cols n  = warp_n*32+ni*8+(lane%4)*2, n+1
    const int er = lane >> 2;
    const int ec = (lane & 3) * 2;
    float ws[4][2];
    #pragma unroll
    for (int ni = 0; ni < 4; ni++) {
        const int n = bn + warp_n * 32 + ni * 8 + ec;
        ws[ni][0] = g_wsq[n];
        ws[ni][1] = g_wsq[n + 1];
    }
    #pragma unroll
    for (int mi = 0; mi < 4; mi++) {
        const int r0 = bm + warp_m * 64 + mi * 16 + er;
        const int r1 = r0 + 8;
        const float xs0 = g_xsq[r0];
        const float xs1 = g_xsq[r1];
        float* row0 = out + (size_t)r0 * CROWS + bn + warp_n * 32 + ec;
        float* row1 = out + (size_t)r1 * CROWS + bn + warp_n * 32 + ec;
        #pragma unroll
        for (int ni = 0; ni < 4; ni++) {
            float2 o0, o1;
            o0.x = fmaf(-2.0f, acc[mi][ni][0], xs0 + ws[ni][0]);
            o0.y = fmaf(-2.0f, acc[mi][ni][1], xs0 + ws[ni][1]);
            o1.x = fmaf(-2.0f, acc[mi][ni][2], xs1 + ws[ni][0]);
            o1.y = fmaf(-2.0f, acc[mi][ni][3], xs1 + ws[ni][1]);
            *reinterpret_cast<float2*>(row0 + ni * 8) = o0;
            *reinterpret_cast<float2*>(row1 + ni * 8) = o1;
        }
    }
}

// ---------------------------------------------------------------------------
extern "C" void kernel_launch(void* const* d_in, const int* in_sizes, int n_in,
                              void* d_out, int out_size) {
    const float* x = (const float*)d_in[0];   // [N, D]
    const float* w = (const float*)d_in[1];   // [C, D]
    float* out = (float*)d_out;               // [N, C]

    static bool attr_set = false;
    if (!attr_set) {
        cudaFuncSetAttribute(mma_dist_kernel,
                             cudaFuncAttributeMaxDynamicSharedMemorySize, SMEM_NEED);
        attr_set = true;
    }

    // 1) split-bf16 conversion + norms (warp per row)
    const int total_rows = NROWS + CROWS;
    const int blocks = (total_rows * 32 + 255) / 256;
    convert_kernel<<<blocks, 256>>>(x, w);

    // 2) tensor-core (mma.sync) distance GEMM
    dim3 grid(CROWS / BN, NROWS / BM);  // (8, 1024)
    mma_dist_kernel<<<grid, 256, SMEM_NEED>>>(out);
}

// round 6
// speedup vs baseline: 5.5028x; 2.4739x over previous
#include <cuda_runtime.h>
#include <cuda_bf16.h>
#include <cstdint>

// Problem constants (fixed: N=131072, C=1024, D=128)
#define NROWS 131072
#define CROWS 1024
#define DDIM  128

#define BM 128
#define BN 128
// whole K=128 bf16 resident: 128 rows x 256B = 32KB per matrix
#define SMEM_NEED 65536

// ---------------------------------------------------------------------------
// Device scratch (no cudaMalloc allowed)
// ---------------------------------------------------------------------------
__device__ float g_xsq[NROWS];
__device__ float g_wsq[CROWS];
__device__ __nv_bfloat16 g_xb[(size_t)NROWS * DDIM];  // bf16(x) (hi only)
__device__ __nv_bfloat16 g_wb[(size_t)CROWS * DDIM];

// ---------------------------------------------------------------------------
// PTX helpers — base-target-safe only (NO tcgen05: harness targets plain sm_103)
// ---------------------------------------------------------------------------
__device__ __forceinline__ uint32_t smem_u32(const void* p) {
    uint32_t a;
    asm("{ .reg .u64 t; cvta.to.shared.u64 t, %1; cvt.u32.u64 %0, t; }"
        : "=r"(a) : "l"(p));
    return a;
}

__device__ __forceinline__ void cp_async16(uint32_t dst, const void* src) {
    asm volatile("cp.async.cg.shared.global [%0], [%1], 16;"
                 :: "r"(dst), "l"(src));
}
#define CP_COMMIT()  asm volatile("cp.async.commit_group;" ::: "memory")
#define CP_WAIT0()   asm volatile("cp.async.wait_group 0;" ::: "memory")

__device__ __forceinline__ void ldsm_x4(uint32_t& r0, uint32_t& r1,
                                        uint32_t& r2, uint32_t& r3, uint32_t a) {
    asm volatile("ldmatrix.sync.aligned.m8n8.x4.shared.b16 {%0,%1,%2,%3}, [%4];"
                 : "=r"(r0), "=r"(r1), "=r"(r2), "=r"(r3) : "r"(a));
}
__device__ __forceinline__ void ldsm_x2(uint32_t& r0, uint32_t& r1, uint32_t a) {
    asm volatile("ldmatrix.sync.aligned.m8n8.x2.shared.b16 {%0,%1}, [%2];"
                 : "=r"(r0), "=r"(r1) : "r"(a));
}

__device__ __forceinline__ void mma16816(float* c, const uint32_t* a,
                                         const uint32_t* b) {
    asm volatile(
        "mma.sync.aligned.m16n8k16.row.col.f32.bf16.bf16.f32 "
        "{%0,%1,%2,%3}, {%4,%5,%6,%7}, {%8,%9}, {%0,%1,%2,%3};"
        : "+f"(c[0]), "+f"(c[1]), "+f"(c[2]), "+f"(c[3])
        : "r"(a[0]), "r"(a[1]), "r"(a[2]), "r"(a[3]), "r"(b[0]), "r"(b[1]));
}

__device__ __forceinline__ void stcs_f2(float* p, float2 v) {
    asm volatile("st.global.cs.v2.f32 [%0], {%1,%2};" :: "l"(p), "f"(v.x), "f"(v.y)
                 : "memory");
}

// 256B-pitch row swizzle: unit u (16B units, 0..15) XOR (row & 7).
// Keeps the 8 addresses of each ldmatrix phase on distinct bank groups.
__device__ __forceinline__ uint32_t tile_off(int row, int u) {
    return (uint32_t)(row * 256 + ((u ^ (row & 7)) << 4));
}

// ---------------------------------------------------------------------------
// Kernel 1: fp32 -> bf16 conversion + exact fp32 row norms. One warp per row.
// ---------------------------------------------------------------------------
__global__ __launch_bounds__(256)
void convert_kernel(const float* __restrict__ x, const float* __restrict__ w) {
    const int gwarp = (blockIdx.x * blockDim.x + threadIdx.x) >> 5;
    const int lane  = threadIdx.x & 31;
    if (gwarp >= NROWS + CROWS) return;

    const bool isx = gwarp < NROWS;
    const int r = isx ? gwarp : gwarp - NROWS;
    const float* base = isx ? (x + (size_t)r * DDIM) : (w + (size_t)r * DDIM);

    float4 v = reinterpret_cast<const float4*>(base)[lane];
    float f[4] = {v.x, v.y, v.z, v.w};

    float s = f[0]*f[0] + f[1]*f[1] + f[2]*f[2] + f[3]*f[3];
    #pragma unroll
    for (int o = 16; o > 0; o >>= 1)
        s += __shfl_xor_sync(0xffffffffu, s, o);

    uint32_t hb[4];
    #pragma unroll
    for (int i = 0; i < 4; i++)
        hb[i] = (uint32_t)__bfloat16_as_ushort(__float2bfloat16_rn(f[i]));
    uint2 H;
    H.x = hb[0] | (hb[1] << 16); H.y = hb[2] | (hb[3] << 16);

    __nv_bfloat16* dst = isx ? (g_xb + (size_t)r * DDIM) : (g_wb + (size_t)r * DDIM);
    reinterpret_cast<uint2*>(dst)[lane] = H;

    if (lane == 0) {
        if (isx) g_xsq[r] = s; else g_wsq[r] = s;
    }
}

// ---------------------------------------------------------------------------
// Kernel 2: bf16 GEMM (mma.sync m16n8k16) + fused distance epilogue.
// CTA 128x128, full K=128 resident in smem, single load phase + single sync.
// 8 warps: warp_m in {0,1} (64 rows), warp_n in {0..3} (32 cols).
// Latency hidden across 2 CTAs/SM.
// ---------------------------------------------------------------------------
__global__ __launch_bounds__(256, 2)
void mma_dist_kernel(float* __restrict__ out) {
    extern __shared__ char sdyn[];
    const uint32_t Ab = smem_u32(sdyn);
    const uint32_t Bb = Ab + 32768;

    const int tid    = threadIdx.x;
    const int lane   = tid & 31;
    const int wid    = tid >> 5;
    const int warp_m = wid & 1;
    const int warp_n = wid >> 1;
    const int bn     = blockIdx.x * BN;   // prototype tiles (8)
    const int bm     = blockIdx.y * BM;   // x tiles (1024)

    // ---- Load whole A and B tiles (2048 16B units each; 8 per thread each) ----
    {
        const __nv_bfloat16* srcA = g_xb + (size_t)bm * DDIM;
        const __nv_bfloat16* srcB = g_wb + (size_t)bn * DDIM;
        #pragma unroll
        for (int i = 0; i < 8; i++) {
            const int c = tid + i * 256;     // 0..2047
            const int r = c >> 4;            // row 0..127
            const int u = c & 15;            // 16B unit within 256B row
            const uint32_t off = tile_off(r, u);
            cp_async16(Ab + off, srcA + r * DDIM + u * 8);
            cp_async16(Bb + off, srcB + r * DDIM + u * 8);
        }
        CP_COMMIT();
    }

    float acc[4][4][4];
    #pragma unroll
    for (int mi = 0; mi < 4; mi++)
        #pragma unroll
        for (int ni = 0; ni < 4; ni++)
            #pragma unroll
            for (int q = 0; q < 4; q++)
                acc[mi][ni][q] = 0.0f;

    // ldmatrix lane-address components
    const int a_row = warp_m * 64 + (lane & 15);   // + mi*16
    const int a_u0  = lane >> 4;                   // + ks*2
    const int b_row = warp_n * 32 + (lane & 7);    // + ni*8
    const int b_u0  = (lane >> 3) & 1;             // + ks*2

    CP_WAIT0();
    __syncthreads();

    #pragma unroll
    for (int ks = 0; ks < 8; ks++) {
        uint32_t a[4][4], b[4][2];
        #pragma unroll
        for (int mi = 0; mi < 4; mi++)
            ldsm_x4(a[mi][0], a[mi][1], a[mi][2], a[mi][3],
                    Ab + tile_off(a_row + mi * 16, a_u0 + ks * 2));
        #pragma unroll
        for (int ni = 0; ni < 4; ni++)
            ldsm_x2(b[ni][0], b[ni][1],
                    Bb + tile_off(b_row + ni * 8, b_u0 + ks * 2));
        #pragma unroll
        for (int mi = 0; mi < 4; mi++)
            #pragma unroll
            for (int ni = 0; ni < 4; ni++)
                mma16816(acc[mi][ni], a[mi], b[ni]);
    }

    // ---- Epilogue: dist = xsq + wsq - 2*acc (streaming stores) ----
    const int er = lane >> 2;
    const int ec = (lane & 3) * 2;
    float ws[4][2];
    #pragma unroll
    for (int ni = 0; ni < 4; ni++) {
        const int n = bn + warp_n * 32 + ni * 8 + ec;
        ws[ni][0] = g_wsq[n];
        ws[ni][1] = g_wsq[n + 1];
    }
    #pragma unroll
    for (int mi = 0; mi < 4; mi++) {
        const int r0 = bm + warp_m * 64 + mi * 16 + er;
        const int r1 = r0 + 8;
        const float xs0 = g_xsq[r0];
        const float xs1 = g_xsq[r1];
        float* row0 = out + (size_t)r0 * CROWS + bn + warp_n * 32 + ec;
        float* row1 = out + (size_t)r1 * CROWS + bn + warp_n * 32 + ec;
        #pragma unroll
        for (int ni = 0; ni < 4; ni++) {
            float2 o0, o1;
            o0.x = fmaf(-2.0f, acc[mi][ni][0], xs0 + ws[ni][0]);
            o0.y = fmaf(-2.0f, acc[mi][ni][1], xs0 + ws[ni][1]);
            o1.x = fmaf(-2.0f, acc[mi][ni][2], xs1 + ws[ni][0]);
            o1.y = fmaf(-2.0f, acc[mi][ni][3], xs1 + ws[ni][1]);
            stcs_f2(row0 + ni * 8, o0);
            stcs_f2(row1 + ni * 8, o1);
        }
    }
}

// ---------------------------------------------------------------------------
extern "C" void kernel_launch(void* const* d_in, const int* in_sizes, int n_in,
                              void* d_out, int out_size) {
    const float* x = (const float*)d_in[0];   // [N, D]
    const float* w = (const float*)d_in[1];   // [C, D]
    float* out = (float*)d_out;               // [N, C]

    static bool attr_set = false;
    if (!attr_set) {
        cudaFuncSetAttribute(mma_dist_kernel,
                             cudaFuncAttributeMaxDynamicSharedMemorySize, SMEM_NEED);
        attr_set = true;
    }

    // 1) bf16 conversion + norms (warp per row)
    const int total_rows = NROWS + CROWS;
    const int blocks = (total_rows * 32 + 255) / 256;
    convert_kernel<<<blocks, 256>>>(x, w);

    // 2) tensor-core (mma.sync) distance GEMM
    dim3 grid(CROWS / BN, NROWS / BM);  // (8, 1024)
    mma_dist_kernel<<<grid, 256, SMEM_NEED>>>(out);
}